// round 4
// baseline (speedup 1.0000x reference)
#include <cuda_runtime.h>
#include <cstdint>

// Problem constants (match reference)
#define U_DIM 2000
#define I_DIM 2000
#define K_DIM 32
#define B_DIM 16384
#define NEIGHBORHOOD 32.0f

#define THREADS 256
#define WARPS_PER_BLOCK (THREADS / 32)
#define SPW 2   // samples per warp
#define SAMPLES_PER_BLOCK (WARPS_PER_BLOCK * SPW)   // 16

// One warp handles SPW=2 samples; lane k handles neighbor k of each.
// Grid = 1024 blocks -> ~7 blocks/SM resident (occ ~85%) while keeping
// MLP=6 independent loads per warp. The binding resource is the per-SM
// L1tex wavefront pipe (scattered gathers replay at ~2 cyc/line); the goal
// of this config is to keep that pipe >95% fed.
__global__ void __launch_bounds__(THREADS) item_reg_kernel(
    const float* __restrict__ rating_matrix,  // [U, I]
    const int*   __restrict__ qtus,           // [U, I, K]
    const float* __restrict__ weight,         // [I, I]
    const float* __restrict__ b_user,         // [U]
    const float* __restrict__ b_item,         // [I]
    const int*   __restrict__ users,          // [B]
    const int*   __restrict__ items,          // [B]
    float*       __restrict__ out)            // [B]
{
    __shared__ float s_bitem[I_DIM];

    // Cooperative coalesced fill of b_item into smem (2000 floats = 8KB).
    #pragma unroll
    for (int i = threadIdx.x; i < I_DIM; i += THREADS)
        s_bitem[i] = b_item[i];

    const int warp_in_block = threadIdx.x >> 5;
    const int lane          = threadIdx.x & 31;
    const int b0 = (blockIdx.x * WARPS_PER_BLOCK + warp_in_block) * SPW;

    // ---- sample indices: vectorized 8B loads (b0 is even) ----
    const int2 uv = *(const int2*)(users + b0);
    const int2 tv = *(const int2*)(items + b0);
    const int u[SPW] = { uv.x, uv.y };
    const int t[SPW] = { tv.x, tv.y };

    // ---- independent: neighbor-index rows + user biases, all in flight ----
    int j[SPW];
    float bu[SPW];
    #pragma unroll
    for (int s = 0; s < SPW; s++) {
        const long long qbase = ((long long)u[s] * I_DIM + t[s]) * K_DIM;
        j[s]  = __ldg(&qtus[qbase + lane]);       // coalesced 128B line
        bu[s] = __ldg(&b_user[u[s]]);             // uniform broadcast
    }

    __syncthreads();   // smem b_item ready (placed late to overlap fill)

    // ---- scattered gathers: 4 independent LDGs in flight ----
    float w[SPW], r[SPW];
    #pragma unroll
    for (int s = 0; s < SPW; s++) {
        w[s] = __ldg(&weight[(long long)j[s] * I_DIM + t[s]]);
        r[s] = __ldg(&rating_matrix[(long long)u[s] * I_DIM + j[s]]);
    }

    // ---- compute + interleaved warp reductions ----
    float v[SPW];
    #pragma unroll
    for (int s = 0; s < SPW; s++)
        v[s] = w[s] * (r[s] - bu[s] - s_bitem[j[s]]);

    #pragma unroll
    for (int off = 16; off > 0; off >>= 1) {
        #pragma unroll
        for (int s = 0; s < SPW; s++)
            v[s] += __shfl_down_sync(0xFFFFFFFFu, v[s], off);
    }

    if (lane == 0) {
        #pragma unroll
        for (int s = 0; s < SPW; s++)
            out[b0 + s] = bu[s] + s_bitem[t[s]] + v[s] * (1.0f / NEIGHBORHOOD);
    }
}

extern "C" void kernel_launch(void* const* d_in, const int* in_sizes, int n_in,
                              void* d_out, int out_size)
{
    const float* rating_matrix = (const float*)d_in[0];
    const int*   qtus          = (const int*)  d_in[1];
    const float* weight        = (const float*)d_in[2];
    const float* b_user        = (const float*)d_in[3];
    const float* b_item        = (const float*)d_in[4];
    const int*   users         = (const int*)  d_in[5];
    const int*   items         = (const int*)  d_in[6];
    float* out = (float*)d_out;

    const int blocks = B_DIM / SAMPLES_PER_BLOCK;  // 1024
    item_reg_kernel<<<blocks, THREADS>>>(rating_matrix, qtus, weight, b_user,
                                         b_item, users, items, out);
}

// round 5
// speedup vs baseline: 1.0489x; 1.0489x over previous
#include <cuda_runtime.h>
#include <cstdint>

// Problem constants (match reference)
#define U_DIM 2000
#define I_DIM 2000
#define K_DIM 32
#define B_DIM 16384
#define NEIGHBORHOOD 32.0f

#define THREADS 128
#define WARPS_PER_BLOCK (THREADS / 32)      // 4
#define SPW 8                               // samples per warp
#define SAMPLES_PER_BLOCK (WARPS_PER_BLOCK * SPW)   // 32

// One warp handles SPW=8 samples; lane k handles neighbor k of each.
// All 8 samples' loads are issued in dependency-ordered batches: 8 qtus rows,
// then 16 scattered gathers, all independent and in flight together (~24 LDGs
// per warp outstanding). 512 blocks -> ~3.5 blocks/SM, low occupancy but max
// ILP, which was the only config axis that moved the needle (R3).
// All offsets are 32-bit (max 128M elements).
__global__ void __launch_bounds__(THREADS) item_reg_kernel(
    const float* __restrict__ rating_matrix,  // [U, I]
    const int*   __restrict__ qtus,           // [U, I, K]
    const float* __restrict__ weight,         // [I, I]
    const float* __restrict__ b_user,         // [U]
    const float* __restrict__ b_item,         // [I]
    const int*   __restrict__ users,          // [B]
    const int*   __restrict__ items,          // [B]
    float*       __restrict__ out)            // [B]
{
    __shared__ float s_bitem[I_DIM];

    // Cooperative coalesced fill of b_item into smem (2000 floats = 8KB).
    #pragma unroll
    for (int i = threadIdx.x; i < I_DIM; i += THREADS)
        s_bitem[i] = b_item[i];

    const int warp_in_block = threadIdx.x >> 5;
    const int lane          = threadIdx.x & 31;
    const int b0 = (blockIdx.x * WARPS_PER_BLOCK + warp_in_block) * SPW;

    // ---- sample indices: two 16B vector loads each ----
    const int4 uv0 = *(const int4*)(users + b0);
    const int4 uv1 = *(const int4*)(users + b0 + 4);
    const int4 tv0 = *(const int4*)(items + b0);
    const int4 tv1 = *(const int4*)(items + b0 + 4);
    const int u[SPW] = { uv0.x, uv0.y, uv0.z, uv0.w, uv1.x, uv1.y, uv1.z, uv1.w };
    const int t[SPW] = { tv0.x, tv0.y, tv0.z, tv0.w, tv1.x, tv1.y, tv1.z, tv1.w };

    // ---- batch: 8 independent coalesced qtus rows + 8 uniform bias loads ----
    int   j[SPW];
    float bu[SPW];
    #pragma unroll
    for (int s = 0; s < SPW; s++) {
        const unsigned ut = (unsigned)u[s] * I_DIM + (unsigned)t[s];
        j[s]  = __ldg(&qtus[ut * K_DIM + lane]);   // 128B coalesced line
        bu[s] = __ldg(&b_user[u[s]]);
    }

    __syncthreads();   // smem b_item ready

    // ---- batch: 16 independent scattered gathers in flight ----
    float w[SPW], r[SPW];
    #pragma unroll
    for (int s = 0; s < SPW; s++) {
        w[s] = __ldg(&weight[(unsigned)j[s] * I_DIM + (unsigned)t[s]]);
        r[s] = __ldg(&rating_matrix[(unsigned)u[s] * I_DIM + (unsigned)j[s]]);
    }

    // ---- compute + interleaved warp reductions ----
    float v[SPW];
    #pragma unroll
    for (int s = 0; s < SPW; s++)
        v[s] = w[s] * (r[s] - bu[s] - s_bitem[j[s]]);

    #pragma unroll
    for (int off = 16; off > 0; off >>= 1) {
        #pragma unroll
        for (int s = 0; s < SPW; s++)
            v[s] += __shfl_down_sync(0xFFFFFFFFu, v[s], off);
    }

    if (lane == 0) {
        #pragma unroll
        for (int s = 0; s < SPW; s++)
            out[b0 + s] = bu[s] + s_bitem[t[s]] + v[s] * (1.0f / NEIGHBORHOOD);
    }
}

extern "C" void kernel_launch(void* const* d_in, const int* in_sizes, int n_in,
                              void* d_out, int out_size)
{
    const float* rating_matrix = (const float*)d_in[0];
    const int*   qtus          = (const int*)  d_in[1];
    const float* weight        = (const float*)d_in[2];
    const float* b_user        = (const float*)d_in[3];
    const float* b_item        = (const float*)d_in[4];
    const int*   users         = (const int*)  d_in[5];
    const int*   items         = (const int*)  d_in[6];
    float* out = (float*)d_out;

    const int blocks = B_DIM / SAMPLES_PER_BLOCK;  // 512
    item_reg_kernel<<<blocks, THREADS>>>(rating_matrix, qtus, weight, b_user,
                                         b_item, users, items, out);
}